// round 2
// baseline (speedup 1.0000x reference)
#include <cuda_runtime.h>

#define D     256
#define BOOK  8192
#define MT    128     // queries per CTA
#define NT    128     // codes per chunk
#define KT    16      // K slice for code double-buffer
#define HW    1024    // 32*32 spatial positions per batch

// zs: 256*128 floats (128KB). es: 2 * KT * (2*NT) floats duplicated (32KB).
#define SMEM_BYTES ((D * MT + 2 * KT * 2 * NT) * 4)   // 163840 B

__device__ float g_enorm[BOOK];

// ||e||^2 per codebook row. One 64-thread block per code.
__global__ void __launch_bounds__(64) enorm_kernel(const float* __restrict__ cb) {
    int c = blockIdx.x;
    float4 v = reinterpret_cast<const float4*>(cb + (size_t)c * D)[threadIdx.x];
    float s = v.x * v.x + v.y * v.y + v.z * v.z + v.w * v.w;
#pragma unroll
    for (int o = 16; o > 0; o >>= 1) s += __shfl_down_sync(0xffffffffu, s, o);
    __shared__ float sh[2];
    if ((threadIdx.x & 31) == 0) sh[threadIdx.x >> 5] = s;
    __syncthreads();
    if (threadIdx.x == 0) g_enorm[c] = sh[0] + sh[1];
}

// packed fp32x2 FMA: acc(2 lanes) += a(2 lanes) * b(2 lanes)
__device__ __forceinline__ void ffma2(unsigned long long& acc,
                                      unsigned long long a,
                                      unsigned long long b) {
    asm("fma.rn.f32x2 %0, %1, %2, %0;" : "+l"(acc) : "l"(a), "l"(b));
}

__device__ __forceinline__ unsigned long long dup2(float v) {
    unsigned int b = __float_as_uint(v);
    return ((unsigned long long)b << 32) | b;
}

extern __shared__ float smem[];

__global__ void __launch_bounds__(256, 1) vq_kernel(
    const float* __restrict__ ze, const float* __restrict__ cb,
    float* __restrict__ out, int N, int write_idx)
{
    float* zs = smem;               // [256][128] query tile, transposed (k-major)
    float* es = smem + D * MT;      // [2][KT][2*NT] code slice, duplicated pairs

    const int tid = threadIdx.x;
    const int tx = tid & 15;
    const int ty = tid >> 4;
    const int n0 = blockIdx.x * MT;
    const int b   = n0 / HW;
    const int hwb = n0 % HW;
    const float* zbase = ze + (size_t)b * D * HW + hwb;

    // Load z tile: zs[k][q] = z_e[b][k][hwb+q]  (coalesced: q contiguous in gmem)
    {
        int w = tid >> 5, l = tid & 31;
        for (int k = w; k < D; k += 8) {
            float4 v = *reinterpret_cast<const float4*>(zbase + (size_t)k * HW + l * 4);
            *reinterpret_cast<float4*>(&zs[k * MT + l * 4]) = v;
        }
    }

    const int qa = ty * 4, qb = 64 + ty * 4;    // 8 query rows per thread (2 groups of 4)
    const int ca = tx * 4, cc = 64 + tx * 4;    // 8 code cols per thread

    float bestv[8];
    int   besti[8];
#pragma unroll
    for (int i = 0; i < 8; i++) { bestv[i] = 3.0e38f; besti[i] = 0; }

    const int cld   = tid >> 1;          // code row this thread stages
    const int khalf = (tid & 1) * 8;     // k offset within slice (KT=16, 8 each)

    __syncthreads();

    for (int c0 = 0; c0 < BOOK; c0 += NT) {
        // acc packed along queries: acc2[ii][j] holds (q=2ii, q=2ii+1) for code j
        unsigned long long acc2[4][8];
#pragma unroll
        for (int i = 0; i < 4; i++)
#pragma unroll
            for (int j = 0; j < 8; j++) acc2[i][j] = 0ull;

        // Preload slice ks=0 into buffer 0, duplicated: es[k][2c]=es[k][2c+1]=e
        {
            const float* src = cb + (size_t)(c0 + cld) * D + khalf;
#pragma unroll
            for (int v4 = 0; v4 < 2; v4++) {
                float4 v = *reinterpret_cast<const float4*>(src + v4 * 4);
                unsigned long long* dst =
                    (unsigned long long*)&es[(khalf + v4 * 4) * (2 * NT) + 2 * cld];
                dst[0 * NT]           = dup2(v.x);
                dst[1 * NT]           = dup2(v.y);
                dst[2 * NT]           = dup2(v.z);
                dst[3 * NT]           = dup2(v.w);
            }
        }
        __syncthreads();

        int buf = 0;
        for (int ks = 0; ks < D; ks += KT) {
            if (ks + KT < D) {  // prefetch next slice into other buffer
                float* ed = es + (buf ^ 1) * KT * 2 * NT;
                const float* src = cb + (size_t)(c0 + cld) * D + ks + KT + khalf;
#pragma unroll
                for (int v4 = 0; v4 < 2; v4++) {
                    float4 v = *reinterpret_cast<const float4*>(src + v4 * 4);
                    unsigned long long* dst =
                        (unsigned long long*)&ed[(khalf + v4 * 4) * (2 * NT) + 2 * cld];
                    dst[0 * NT]           = dup2(v.x);
                    dst[1 * NT]           = dup2(v.y);
                    dst[2 * NT]           = dup2(v.z);
                    dst[3 * NT]           = dup2(v.w);
                }
            }
            const float* eb = es + buf * KT * 2 * NT;
#pragma unroll 4
            for (int k = 0; k < KT; k++) {
                const float* zr = &zs[(ks + k) * MT];
                // a: query pairs, adjacent in zs -> direct 64-bit packed loads
                ulonglong2 a01 = *reinterpret_cast<const ulonglong2*>(zr + qa);
                ulonglong2 a23 = *reinterpret_cast<const ulonglong2*>(zr + qb);
                unsigned long long ap[4] = {a01.x, a01.y, a23.x, a23.y};
                // b: duplicated pairs (e,e) staged in smem
                const float* er = eb + k * (2 * NT);
                ulonglong2 b01 = *reinterpret_cast<const ulonglong2*>(er + 2 * ca);
                ulonglong2 b23 = *reinterpret_cast<const ulonglong2*>(er + 2 * ca + 4);
                ulonglong2 b45 = *reinterpret_cast<const ulonglong2*>(er + 2 * cc);
                ulonglong2 b67 = *reinterpret_cast<const ulonglong2*>(er + 2 * cc + 4);
                unsigned long long bp[8] = {b01.x, b01.y, b23.x, b23.y,
                                            b45.x, b45.y, b67.x, b67.y};
#pragma unroll
                for (int i = 0; i < 4; i++)
#pragma unroll
                    for (int j = 0; j < 8; j++)
                        ffma2(acc2[i][j], ap[i], bp[j]);
            }
            __syncthreads();
            buf ^= 1;
        }

        // Score = ||e||^2 - 2*dot ; running argmin.
        // Codes ascend within the j loop; chunks ascend -> strict '<' keeps
        // the first occurrence, matching jnp.argmin.
#pragma unroll
        for (int j = 0; j < 8; j++) {
            int c = c0 + (j < 4 ? ca + j : cc + (j - 4));
            float en = __ldg(&g_enorm[c]);
#pragma unroll
            for (int ii = 0; ii < 4; ii++) {
                unsigned long long p = acc2[ii][j];
                float dlo = __uint_as_float((unsigned int)p);
                float dhi = __uint_as_float((unsigned int)(p >> 32));
                int ilo = ii * 2;       // query index within this thread's 8
                int ihi = ii * 2 + 1;
                float slo = fmaf(-2.0f, dlo, en);
                float shi = fmaf(-2.0f, dhi, en);
                if (slo < bestv[ilo]) { bestv[ilo] = slo; besti[ilo] = c; }
                if (shi < bestv[ihi]) { bestv[ihi] = shi; besti[ihi] = c; }
            }
        }
    }

    // Cross-thread argmin reduction (reuse zs region)
    float* redv = zs;                         // [128][16]
    int*   redi = (int*)(zs + MT * 16);       // [128][16]
    int*   bi   = (int*)(zs + MT * 32);       // [128]
    __syncthreads();
#pragma unroll
    for (int i = 0; i < 8; i++) {
        int q = (i < 4) ? (qa + i) : (qb + i - 4);
        redv[q * 16 + tx] = bestv[i];
        redi[q * 16 + tx] = besti[i];
    }
    __syncthreads();
    if (tid < MT) {
        int q = tid;
        float bv = redv[q * 16];
        int   bx = redi[q * 16];
#pragma unroll
        for (int t = 1; t < 16; t++) {
            float v  = redv[q * 16 + t];
            int   ix = redi[q * 16 + t];
            if (v < bv || (v == bv && ix < bx)) { bv = v; bx = ix; }
        }
        bi[q] = bx;
        if (write_idx) out[(size_t)N * D + n0 + q] = (float)bx;
    }
    __syncthreads();

    // Gather z_q rows: out[n] = codebook[bi[q]] (coalesced float4 copy)
    const float4* cb4  = reinterpret_cast<const float4*>(cb);
    float4*       out4 = reinterpret_cast<float4*>(out);
    for (int e = tid; e < MT * (D / 4); e += 256) {
        int q = e >> 6;       // row within tile
        int p = e & 63;       // float4 within row
        int idx = bi[q];
        out4[(size_t)(n0 + q) * (D / 4) + p] = cb4[(size_t)idx * (D / 4) + p];
    }
}

extern "C" void kernel_launch(void* const* d_in, const int* in_sizes, int n_in,
                              void* d_out, int out_size) {
    const float* ze = (const float*)d_in[0];
    const float* cb = (const float*)d_in[1];
    float* out = (float*)d_out;

    int N = in_sizes[0] / D;                       // 16384
    int write_idx = (out_size >= N * D + N) ? 1 : 0;

    cudaFuncSetAttribute(vq_kernel, cudaFuncAttributeMaxDynamicSharedMemorySize,
                         SMEM_BYTES);

    enorm_kernel<<<BOOK, 64>>>(cb);
    vq_kernel<<<N / MT, 256, SMEM_BYTES>>>(ze, cb, out, N, write_idx);
}

// round 5
// speedup vs baseline: 3.7790x; 3.7790x over previous
#include <cuda_runtime.h>
#include <cuda_fp16.h>
#include <cstdint>

#define D      256
#define BOOK   8192
#define NTOT   16384
#define HW     1024
#define MT     128              // queries per CTA
#define NT     64               // codes per chunk
#define KTOT   768              // 3-pass split folded into K
#define KS     128              // k per pipelined slice
#define SLICES_PER_CHUNK (KTOT / KS)          // 6
#define CHUNKS (BOOK / NT)                    // 128
#define GTOT   (CHUNKS * SLICES_PER_CHUNK)    // 768 slices

#define A_BYTES (8 * 48 * 32 * 16)            // 196608: [mt][kt][lane][16B]
#define B_BYTES (NT * KS * 2)                 // 16384 per buffer
#define DYN_SMEM (A_BYTES + 2 * B_BYTES)      // 229376

__device__ __half g_ecat[BOOK][KTOT];   // [e1 | e2 | e1]
__device__ __half g_zcat[NTOT][KTOT];   // [z1 | z1 | z2]
__device__ float  g_enorm[BOOK];

// ---------------- prep: codebook split + norms ----------------
__global__ void __launch_bounds__(64) eprep_kernel(const float* __restrict__ cb) {
    int c = blockIdx.x, t = threadIdx.x;
    float4 v = reinterpret_cast<const float4*>(cb + (size_t)c * D)[t];
    float f[4] = {v.x, v.y, v.z, v.w};
#pragma unroll
    for (int i = 0; i < 4; i++) {
        __half h1 = __float2half_rn(f[i]);
        __half h2 = __float2half_rn(f[i] - __half2float(h1));
        int k = t * 4 + i;
        g_ecat[c][k]       = h1;
        g_ecat[c][512 + k] = h1;
        g_ecat[c][256 + k] = h2;
    }
    float s = v.x * v.x + v.y * v.y + v.z * v.z + v.w * v.w;
#pragma unroll
    for (int o = 16; o > 0; o >>= 1) s += __shfl_down_sync(0xffffffffu, s, o);
    __shared__ float sh[2];
    if ((t & 31) == 0) sh[t >> 5] = s;
    __syncthreads();
    if (t == 0) g_enorm[c] = sh[0] + sh[1];
}

// ---------------- prep: z NCHW -> rows + split ----------------
__global__ void __launch_bounds__(256) zprep_kernel(const float* __restrict__ ze) {
    __shared__ float zt[D][33];
    int b = blockIdx.x, hw0 = blockIdx.y * 32;
    int tid = threadIdx.x, w = tid >> 5, l = tid & 31;
    for (int k = w; k < D; k += 8)
        zt[k][l] = ze[((size_t)b * D + k) * HW + hw0 + l];
    __syncthreads();
    int r = tid >> 3, seg = tid & 7;           // r: query row (0..31), seg: k block
    int n = b * HW + hw0 + r;
#pragma unroll
    for (int i = 0; i < 32; i++) {
        int k = seg * 32 + i;
        float f = zt[k][r];
        __half h1 = __float2half_rn(f);
        __half h2 = __float2half_rn(f - __half2float(h1));
        g_zcat[n][k]       = h1;
        g_zcat[n][256 + k] = h1;
        g_zcat[n][512 + k] = h2;
    }
}

// ---------------- main GEMM + argmin ----------------
__device__ __forceinline__ void mma16816(float d[4], uint32_t a0, uint32_t a1,
                                         uint32_t a2, uint32_t a3,
                                         uint32_t b0, uint32_t b1) {
    asm volatile(
        "mma.sync.aligned.m16n8k16.row.col.f32.f16.f16.f32 "
        "{%0,%1,%2,%3}, {%4,%5,%6,%7}, {%8,%9}, {%0,%1,%2,%3};"
        : "+f"(d[0]), "+f"(d[1]), "+f"(d[2]), "+f"(d[3])
        : "r"(a0), "r"(a1), "r"(a2), "r"(a3), "r"(b0), "r"(b1));
}

__device__ __forceinline__ void cp16(void* dst, const void* src) {
    uint32_t d;
    asm("{ .reg .u64 t; cvta.to.shared.u64 t, %1; cvt.u32.u64 %0, t; }" : "=r"(d) : "l"(dst));
    asm volatile("cp.async.cg.shared.global [%0], [%1], 16;" :: "r"(d), "l"(src));
}
#define CP_COMMIT() asm volatile("cp.async.commit_group;" ::: "memory")
#define CP_WAIT(n)  asm volatile("cp.async.wait_group %0;" :: "n"(n) : "memory")

// B slice swizzled byte address: row n (256B), kb = byte offset in row (0..255)
__device__ __forceinline__ uint32_t b_addr(int n, int kb) {
    return (uint32_t)(n * 256 + (kb & 0x8F) + ((((kb >> 4) & 7) ^ (n & 7)) << 4));
}

extern __shared__ char dsm[];

__global__ void __launch_bounds__(256, 1) vq_main(
    const float* __restrict__ cb, float* __restrict__ out, int Nq, int write_idx)
{
    __shared__ int s_bi[MT];

    char* As = dsm;                      // fragment-layout A
    char* Bs = dsm + A_BYTES;            // two 16KB B slice buffers
    float* redv = reinterpret_cast<float*>(Bs);            // final reduce (reuse B)
    int*   redi = reinterpret_cast<int*>(Bs + MT * 8 * 4);

    const int tid = threadIdx.x;
    const int lane = tid & 31, w = tid >> 5;
    const int wm = w & 3, wn = w >> 2;   // 4 m-blocks x 2 n-halves
    const int n0 = blockIdx.x * MT;

    // ---- build A fragments in SMEM: A_frag[mt(8)][kt(48)][lane(32)][4xb32]
    for (int i = tid; i < 8 * 48 * 32; i += 256) {
        int la = i & 31, kt = (i >> 5) % 48, mt = (i >> 5) / 48;
        int q  = n0 + mt * 16 + (la >> 2);
        int k0 = kt * 16 + 2 * (la & 3);
        const char* zr = (const char*)&g_zcat[q][0];
        uint4 v;
        v.x = *(const uint32_t*)(zr + 2 * k0);
        v.y = *(const uint32_t*)(zr + 2 * k0 + 16 * KTOT);        // row q+8
        v.z = *(const uint32_t*)(zr + 2 * (k0 + 8));
        v.w = *(const uint32_t*)(zr + 2 * (k0 + 8) + 16 * KTOT);
        *reinterpret_cast<uint4*>(As + (size_t)i * 16) = v;
    }

    float acc[2][4][4];
    float bestv[4];
    int   besti[4];
#pragma unroll
    for (int i = 0; i < 4; i++) { bestv[i] = 3.0e38f; besti[i] = 0; }

    // ---- preload slice 0
    {
        char* bd = Bs;
#pragma unroll
        for (int j = 0; j < 4; j++) {
            int unit = tid + j * 256;
            int n = unit >> 4, u = unit & 15;
            cp16(bd + b_addr(n, u * 16), &g_ecat[n][u * 8]);
        }
        CP_COMMIT();
    }
    __syncthreads();   // A fragments ready (also covers first compute)

    for (int g = 0; g < GTOT; g++) {
        const int buf = g & 1;
        const int chunk = g / SLICES_PER_CHUNK;
        const int s = g - chunk * SLICES_PER_CHUNK;

        if (g + 1 < GTOT) {
            const int gn = g + 1;
            const int cn = gn / SLICES_PER_CHUNK, sn = gn - cn * SLICES_PER_CHUNK;
            char* bd = Bs + (buf ^ 1) * B_BYTES;
            const int c0n = cn * NT, ksn = sn * KS;
#pragma unroll
            for (int j = 0; j < 4; j++) {
                int unit = tid + j * 256;
                int n = unit >> 4, u = unit & 15;
                cp16(bd + b_addr(n, u * 16), &g_ecat[c0n + n][ksn + u * 8]);
            }
            CP_COMMIT();
            CP_WAIT(1);
        } else {
            CP_WAIT(0);
        }
        __syncthreads();   // slice g visible to all

        if (s == 0) {
#pragma unroll
            for (int mt = 0; mt < 2; mt++)
#pragma unroll
                for (int nt = 0; nt < 4; nt++)
#pragma unroll
                    for (int e = 0; e < 4; e++) acc[mt][nt][e] = 0.f;
        }

        const char* bb = Bs + buf * B_BYTES;
#pragma unroll
        for (int ktl = 0; ktl < 8; ktl++) {
            const int kt = s * 8 + ktl;
            uint4 A0 = *reinterpret_cast<const uint4*>(
                As + (((wm * 2 + 0) * 48 + kt) * 32 + lane) * 16);
            uint4 A1 = *reinterpret_cast<const uint4*>(
                As + (((wm * 2 + 1) * 48 + kt) * 32 + lane) * 16);
#pragma unroll
            for (int nt = 0; nt < 4; nt++) {
                int n_loc = wn * 32 + nt * 8 + (lane >> 2);
                int kb0 = ktl * 32 + 4 * (lane & 3);
                uint32_t b0 = *reinterpret_cast<const uint32_t*>(bb + b_addr(n_loc, kb0));
                uint32_t b1 = *reinterpret_cast<const uint32_t*>(bb + b_addr(n_loc, kb0 + 16));
                mma16816(acc[0][nt], A0.x, A0.y, A0.z, A0.w, b0, b1);
                mma16816(acc[1][nt], A1.x, A1.y, A1.z, A1.w, b0, b1);
            }
        }

        if (s == SLICES_PER_CHUNK - 1) {
            // fold chunk scores into running argmin
            const int c0 = chunk * NT + wn * 32 + 2 * (lane & 3);
#pragma unroll
            for (int mt = 0; mt < 2; mt++)
#pragma unroll
                for (int nt = 0; nt < 4; nt++) {
                    int cb0 = c0 + nt * 8;
                    float en0 = __ldg(&g_enorm[cb0]);
                    float en1 = __ldg(&g_enorm[cb0 + 1]);
                    float s0 = fmaf(-2.0f, acc[mt][nt][0], en0);
                    float s1 = fmaf(-2.0f, acc[mt][nt][1], en1);
                    float s2 = fmaf(-2.0f, acc[mt][nt][2], en0);
                    float s3 = fmaf(-2.0f, acc[mt][nt][3], en1);
                    int blo = mt * 2, bhi = mt * 2 + 1;
                    if (s0 < bestv[blo]) { bestv[blo] = s0; besti[blo] = cb0; }
                    if (s1 < bestv[blo]) { bestv[blo] = s1; besti[blo] = cb0 + 1; }
                    if (s2 < bestv[bhi]) { bestv[bhi] = s2; besti[bhi] = cb0; }
                    if (s3 < bestv[bhi]) { bestv[bhi] = s3; besti[bhi] = cb0 + 1; }
                }
        }
        __syncthreads();   // everyone done with buf before it is refilled
    }

    // ---- final cross-thread argmin reduction (lexicographic, first occurrence)
#pragma unroll
    for (int bq = 0; bq < 4; bq++) {
        int q = wm * 32 + (bq >> 1) * 16 + (bq & 1) * 8 + (lane >> 2);
        int slot = wn * 4 + (lane & 3);
        redv[q * 8 + slot] = bestv[bq];
        redi[q * 8 + slot] = besti[bq];
    }
    __syncthreads();
    if (tid < MT) {
        float bv = redv[tid * 8];
        int   bx = redi[tid * 8];
#pragma unroll
        for (int t = 1; t < 8; t++) {
            float v  = redv[tid * 8 + t];
            int   ix = redi[tid * 8 + t];
            if (v < bv || (v == bv && ix < bx)) { bv = v; bx = ix; }
        }
        s_bi[tid] = bx;
        if (write_idx) out[(size_t)Nq * D + n0 + tid] = (float)bx;
    }
    __syncthreads();

    // ---- gather z_q rows from original fp32 codebook
    const float4* cb4 = reinterpret_cast<const float4*>(cb);
    float4* out4 = reinterpret_cast<float4*>(out);
    for (int e = tid; e < MT * (D / 4); e += 256) {
        int q = e >> 6, p = e & 63;
        out4[(size_t)(n0 + q) * (D / 4) + p] = cb4[(size_t)s_bi[q] * (D / 4) + p];
    }
}

extern "C" void kernel_launch(void* const* d_in, const int* in_sizes, int n_in,
                              void* d_out, int out_size) {
    const float* ze = (const float*)d_in[0];
    const float* cb = (const float*)d_in[1];
    float* out = (float*)d_out;

    int Nq = in_sizes[0] / D;                 // 16384
    int nb = Nq / HW;                         // 16
    int write_idx = (out_size >= Nq * D + Nq) ? 1 : 0;

    cudaFuncSetAttribute(vq_main, cudaFuncAttributeMaxDynamicSharedMemorySize, DYN_SMEM);

    eprep_kernel<<<BOOK, 64>>>(cb);
    zprep_kernel<<<dim3(nb, 32), 256>>>(ze);
    vq_main<<<Nq / MT, 256, DYN_SMEM>>>(cb, out, Nq, write_idx);
}

// round 8
// speedup vs baseline: 4.4245x; 1.1708x over previous
#include <cuda_runtime.h>
#include <cuda_fp16.h>
#include <cstdint>

#define D      256
#define BOOK   8192
#define NTOT   16384
#define HW     1024
#define MT     128              // queries per CTA
#define NT     128              // codes per chunk
#define KPHYS  512              // dedup split storage: [z1|z2], [e1|e2]
#define KS     128              // k per pipelined slice
#define SLICES 6                // logical slices per chunk (z1e1 x2, z1e2 x2, z2e1 x2)
#define CHUNKS (BOOK / NT)      // 64
#define GTOT   (CHUNKS * SLICES) // 384

#define A_BYTES (8 * 32 * 32 * 16)            // 131072: [mt(8)][pkt(32)][lane(32)][16B]
#define B_BYTES (NT * 256)                    // 32768 per buffer (128 rows x 256B)
#define DYN_SMEM (A_BYTES + 2 * B_BYTES)      // 196608

__device__ __half g_ecat[BOOK][KPHYS];   // [e1 | e2]
__device__ __half g_zcat[NTOT][KPHYS];   // [z1 | z2]
__device__ float  g_enorm[BOOK];

// ---------------- prep: codebook split + norms ----------------
__global__ void __launch_bounds__(64) eprep_kernel(const float* __restrict__ cb) {
    int c = blockIdx.x, t = threadIdx.x;
    float4 v = reinterpret_cast<const float4*>(cb + (size_t)c * D)[t];
    float f[4] = {v.x, v.y, v.z, v.w};
#pragma unroll
    for (int i = 0; i < 4; i++) {
        __half h1 = __float2half_rn(f[i]);
        __half h2 = __float2half_rn(f[i] - __half2float(h1));
        int k = t * 4 + i;
        g_ecat[c][k]       = h1;
        g_ecat[c][256 + k] = h2;
    }
    float s = v.x * v.x + v.y * v.y + v.z * v.z + v.w * v.w;
#pragma unroll
    for (int o = 16; o > 0; o >>= 1) s += __shfl_down_sync(0xffffffffu, s, o);
    __shared__ float sh[2];
    if ((t & 31) == 0) sh[t >> 5] = s;
    __syncthreads();
    if (t == 0) g_enorm[c] = sh[0] + sh[1];
}

// ---------------- prep: z NCHW -> rows + split ----------------
__global__ void __launch_bounds__(256) zprep_kernel(const float* __restrict__ ze) {
    __shared__ float zt[D][33];
    int b = blockIdx.x, hw0 = blockIdx.y * 32;
    int tid = threadIdx.x, w = tid >> 5, l = tid & 31;
    for (int k = w; k < D; k += 8)
        zt[k][l] = ze[((size_t)b * D + k) * HW + hw0 + l];
    __syncthreads();
    int r = tid >> 3, seg = tid & 7;
    int n = b * HW + hw0 + r;
#pragma unroll
    for (int i = 0; i < 32; i++) {
        int k = seg * 32 + i;
        float f = zt[k][r];
        __half h1 = __float2half_rn(f);
        __half h2 = __float2half_rn(f - __half2float(h1));
        g_zcat[n][k]       = h1;
        g_zcat[n][256 + k] = h2;
    }
}

// ---------------- main GEMM + argmin ----------------
__device__ __forceinline__ void mma16816(float d[4], uint32_t a0, uint32_t a1,
                                         uint32_t a2, uint32_t a3,
                                         uint32_t b0, uint32_t b1) {
    asm volatile(
        "mma.sync.aligned.m16n8k16.row.col.f32.f16.f16.f32 "
        "{%0,%1,%2,%3}, {%4,%5,%6,%7}, {%8,%9}, {%0,%1,%2,%3};"
        : "+f"(d[0]), "+f"(d[1]), "+f"(d[2]), "+f"(d[3])
        : "r"(a0), "r"(a1), "r"(a2), "r"(a3), "r"(b0), "r"(b1));
}

__device__ __forceinline__ void cp16(void* dst, const void* src) {
    uint32_t d;
    asm("{ .reg .u64 t; cvta.to.shared.u64 t, %1; cvt.u32.u64 %0, t; }" : "=r"(d) : "l"(dst));
    asm volatile("cp.async.cg.shared.global [%0], [%1], 16;" :: "r"(d), "l"(src));
}
#define CP_COMMIT() asm volatile("cp.async.commit_group;" ::: "memory")
#define CP_WAIT(n)  asm volatile("cp.async.wait_group %0;" :: "n"(n) : "memory")

// B swizzled byte address: row n (256B), kb = byte offset in row (0..255)
__device__ __forceinline__ uint32_t b_addr(int n, int kb) {
    return (uint32_t)(n * 256 + (kb & 0x8F) + ((((kb >> 4) & 7) ^ (n & 7)) << 4));
}

extern __shared__ char dsm[];

__global__ void __launch_bounds__(256, 1) vq_main(
    const float* __restrict__ cb, float* __restrict__ out, int Nq, int write_idx)
{
    __shared__ int s_bi[MT];

    char* As = dsm;                      // fragment-layout A, dedup [z1|z2]
    char* Bs = dsm + A_BYTES;            // two 32KB B slice buffers
    float* redv = reinterpret_cast<float*>(Bs);            // final reduce (reuse B)
    int*   redi = reinterpret_cast<int*>(Bs + MT * 8 * 4);

    const int tid = threadIdx.x;
    const int lane = tid & 31, w = tid >> 5;
    const int wm = w & 3, wn = w >> 2;   // 4 m-groups x 2 n-halves
    const int n0 = blockIdx.x * MT;

    // ---- build A fragments: A_frag[mt(8)][pkt(32)][lane(32)][4xb32]
    for (int i = tid; i < 8 * 32 * 32; i += 256) {
        int la = i & 31, pkt = (i >> 5) & 31, mt = (i >> 5) >> 5;
        int q  = n0 + mt * 16 + (la >> 2);
        int k0 = pkt * 16 + 2 * (la & 3);
        const char* zr = (const char*)&g_zcat[q][0];
        uint4 v;
        v.x = *(const uint32_t*)(zr + 2 * k0);
        v.y = *(const uint32_t*)(zr + 2 * k0 + 2 * 8 * KPHYS);      // row q+8
        v.z = *(const uint32_t*)(zr + 2 * (k0 + 8));
        v.w = *(const uint32_t*)(zr + 2 * (k0 + 8) + 2 * 8 * KPHYS);
        *reinterpret_cast<uint4*>(As + (size_t)i * 16) = v;
    }

    float acc[2][8][4];
    float bestv[4];
    int   besti[4];
#pragma unroll
    for (int i = 0; i < 4; i++) { bestv[i] = 3.0e38f; besti[i] = 0; }

    // logical slice s -> A physical slice, B k-offset in [e1|e2]
    const int a_ps[SLICES]   = {0, 1, 0, 1, 2, 3};
    const int b_koff[SLICES] = {0, 128, 256, 384, 0, 128};

    // ---- preload slice 0 (chunk 0, s=0 -> e1 first half)
    {
        char* bd = Bs;
#pragma unroll
        for (int j = 0; j < 8; j++) {
            int unit = tid + j * 256;
            int n = unit >> 4, u = unit & 15;
            cp16(bd + b_addr(n, u * 16), &g_ecat[n][u * 8]);
        }
        CP_COMMIT();
    }
    __syncthreads();   // A fragments ready

    for (int g = 0; g < GTOT; g++) {
        const int buf = g & 1;
        const int chunk = g / SLICES;
        const int s = g - chunk * SLICES;

        if (g + 1 < GTOT) {
            const int gn = g + 1;
            const int cn = gn / SLICES, sn = gn - cn * SLICES;
            char* bd = Bs + (buf ^ 1) * B_BYTES;
            const int c0n = cn * NT, ksn = b_koff[sn];
#pragma unroll
            for (int j = 0; j < 8; j++) {
                int unit = tid + j * 256;
                int n = unit >> 4, u = unit & 15;
                cp16(bd + b_addr(n, u * 16), &g_ecat[c0n + n][ksn + u * 8]);
            }
            CP_COMMIT();
            CP_WAIT(1);
        } else {
            CP_WAIT(0);
        }
        __syncthreads();   // slice g visible

        if (s == 0) {
#pragma unroll
            for (int mt = 0; mt < 2; mt++)
#pragma unroll
                for (int nt = 0; nt < 8; nt++)
#pragma unroll
                    for (int e = 0; e < 4; e++) acc[mt][nt][e] = 0.f;
        }

        const char* bb = Bs + buf * B_BYTES;
        const int ps8 = a_ps[s] * 8;
#pragma unroll
        for (int ktl = 0; ktl < 8; ktl++) {
            const int pkt = ps8 + ktl;
            uint4 A0 = *reinterpret_cast<const uint4*>(
                As + (((wm * 2 + 0) * 32 + pkt) * 32 + lane) * 16);
            uint4 A1 = *reinterpret_cast<const uint4*>(
                As + (((wm * 2 + 1) * 32 + pkt) * 32 + lane) * 16);
#pragma unroll
            for (int nt = 0; nt < 8; nt++) {
                int n_loc = wn * 64 + nt * 8 + (lane >> 2);
                int kb0 = ktl * 32 + 4 * (lane & 3);
                uint32_t b0 = *reinterpret_cast<const uint32_t*>(bb + b_addr(n_loc, kb0));
                uint32_t b1 = *reinterpret_cast<const uint32_t*>(bb + b_addr(n_loc, kb0 + 16));
                mma16816(acc[0][nt], A0.x, A0.y, A0.z, A0.w, b0, b1);
                mma16816(acc[1][nt], A1.x, A1.y, A1.z, A1.w, b0, b1);
            }
        }

        if (s == SLICES - 1) {
            // fold chunk scores into running argmin (ascending index order)
            const int c0 = chunk * NT + wn * 64 + 2 * (lane & 3);
#pragma unroll
            for (int mt = 0; mt < 2; mt++)
#pragma unroll
                for (int nt = 0; nt < 8; nt++) {
                    int cb0 = c0 + nt * 8;
                    float en0 = __ldg(&g_enorm[cb0]);
                    float en1 = __ldg(&g_enorm[cb0 + 1]);
                    float s0 = fmaf(-2.0f, acc[mt][nt][0], en0);
                    float s1 = fmaf(-2.0f, acc[mt][nt][1], en1);
                    float s2 = fmaf(-2.0f, acc[mt][nt][2], en0);
                    float s3 = fmaf(-2.0f, acc[mt][nt][3], en1);
                    int blo = mt * 2, bhi = mt * 2 + 1;
                    if (s0 < bestv[blo]) { bestv[blo] = s0; besti[blo] = cb0; }
                    if (s1 < bestv[blo]) { bestv[blo] = s1; besti[blo] = cb0 + 1; }
                    if (s2 < bestv[bhi]) { bestv[bhi] = s2; besti[bhi] = cb0; }
                    if (s3 < bestv[bhi]) { bestv[bhi] = s3; besti[bhi] = cb0 + 1; }
                }
        }
        __syncthreads();   // everyone done with buf before refill
    }

    // ---- final cross-thread argmin reduction (lexicographic, first occurrence)
#pragma unroll
    for (int bq = 0; bq < 4; bq++) {
        int q = wm * 32 + (bq >> 1) * 16 + (bq & 1) * 8 + (lane >> 2);
        int slot = wn * 4 + (lane & 3);
        redv[q * 8 + slot] = bestv[bq];
        redi[q * 8 + slot] = besti[bq];
    }
    __syncthreads();
    if (tid < MT) {
        float bv = redv[tid * 8];
        int   bx = redi[tid * 8];
#pragma unroll
        for (int t = 1; t < 8; t++) {
            float v  = redv[tid * 8 + t];
            int   ix = redi[tid * 8 + t];
            if (v < bv || (v == bv && ix < bx)) { bv = v; bx = ix; }
        }
        s_bi[tid] = bx;
        if (write_idx) out[(size_t)Nq * D + n0 + tid] = (float)bx;
    }
    __syncthreads();

    // ---- gather z_q rows from original fp32 codebook
    const float4* cb4 = reinterpret_cast<const float4*>(cb);
    float4* out4 = reinterpret_cast<float4*>(out);
    for (int e = tid; e < MT * (D / 4); e += 256) {
        int q = e >> 6, p = e & 63;
        out4[(size_t)(n0 + q) * (D / 4) + p] = cb4[(size_t)s_bi[q] * (D / 4) + p];
    }
}

extern "C" void kernel_launch(void* const* d_in, const int* in_sizes, int n_in,
                              void* d_out, int out_size) {
    const float* ze = (const float*)d_in[0];
    const float* cb = (const float*)d_in[1];
    float* out = (float*)d_out;

    int Nq = in_sizes[0] / D;                 // 16384
    int nb = Nq / HW;                         // 16
    int write_idx = (out_size >= Nq * D + Nq) ? 1 : 0;

    cudaFuncSetAttribute(vq_main, cudaFuncAttributeMaxDynamicSharedMemorySize, DYN_SMEM);

    eprep_kernel<<<BOOK, 64>>>(cb);
    zprep_kernel<<<dim3(nb, 32), 256>>>(ze);
    vq_main<<<Nq / MT, 256, DYN_SMEM>>>(cb, out, Nq, write_idx);
}

// round 9
// speedup vs baseline: 4.6511x; 1.0512x over previous
#include <cuda_runtime.h>
#include <cuda_fp16.h>
#include <cstdint>

#define D      256
#define BOOK   8192
#define NTOT   16384
#define HW     1024
#define MT     128              // queries per CTA
#define NT     128              // codes per chunk
#define KPHYS  512              // dedup split storage: [z1|z2], [e1|e2]
#define SLICES 6                // logical slices per chunk
#define CHUNKS (BOOK / NT)      // 64
#define GTOT   (CHUNKS * SLICES) // 384

#define A_BYTES (8 * 32 * 32 * 16)            // 131072: [mt(8)][pkt(32)][lane(32)][16B]
#define B_BYTES (NT * 256)                    // 32768 per buffer (128 rows x 256B)
#define STAGES  3
#define DYN_SMEM (A_BYTES + STAGES * B_BYTES) // 229376

__device__ __half g_ecat[BOOK][KPHYS];   // [e1 | e2]
__device__ __half g_zcat[NTOT][KPHYS];   // [z1 | z2]
__device__ float  g_enorm[BOOK];

// ---------------- prep: codebook split + norms ----------------
__global__ void __launch_bounds__(64) eprep_kernel(const float* __restrict__ cb) {
    int c = blockIdx.x, t = threadIdx.x;
    float4 v = reinterpret_cast<const float4*>(cb + (size_t)c * D)[t];
    float f[4] = {v.x, v.y, v.z, v.w};
#pragma unroll
    for (int i = 0; i < 4; i++) {
        __half h1 = __float2half_rn(f[i]);
        __half h2 = __float2half_rn(f[i] - __half2float(h1));
        int k = t * 4 + i;
        g_ecat[c][k]       = h1;
        g_ecat[c][256 + k] = h2;
    }
    float s = v.x * v.x + v.y * v.y + v.z * v.z + v.w * v.w;
#pragma unroll
    for (int o = 16; o > 0; o >>= 1) s += __shfl_down_sync(0xffffffffu, s, o);
    __shared__ float sh[2];
    if ((t & 31) == 0) sh[t >> 5] = s;
    __syncthreads();
    if (t == 0) g_enorm[c] = sh[0] + sh[1];
}

// ---------------- prep: z NCHW -> rows + split ----------------
__global__ void __launch_bounds__(256) zprep_kernel(const float* __restrict__ ze) {
    __shared__ float zt[D][33];
    int b = blockIdx.x, hw0 = blockIdx.y * 32;
    int tid = threadIdx.x, w = tid >> 5, l = tid & 31;
    for (int k = w; k < D; k += 8)
        zt[k][l] = ze[((size_t)b * D + k) * HW + hw0 + l];
    __syncthreads();
    int r = tid >> 3, seg = tid & 7;
    int n = b * HW + hw0 + r;
#pragma unroll
    for (int i = 0; i < 32; i++) {
        int k = seg * 32 + i;
        float f = zt[k][r];
        __half h1 = __float2half_rn(f);
        __half h2 = __float2half_rn(f - __half2float(h1));
        g_zcat[n][k]       = h1;
        g_zcat[n][256 + k] = h2;
    }
}

// ---------------- main GEMM + argmin ----------------
__device__ __forceinline__ void mma16816(float d[4], uint32_t a0, uint32_t a1,
                                         uint32_t a2, uint32_t a3,
                                         uint32_t b0, uint32_t b1) {
    asm volatile(
        "mma.sync.aligned.m16n8k16.row.col.f32.f16.f16.f32 "
        "{%0,%1,%2,%3}, {%4,%5,%6,%7}, {%8,%9}, {%0,%1,%2,%3};"
        : "+f"(d[0]), "+f"(d[1]), "+f"(d[2]), "+f"(d[3])
        : "r"(a0), "r"(a1), "r"(a2), "r"(a3), "r"(b0), "r"(b1));
}

__device__ __forceinline__ void ldmatrix_x4(uint32_t& r0, uint32_t& r1,
                                            uint32_t& r2, uint32_t& r3,
                                            uint32_t addr) {
    asm volatile("ldmatrix.sync.aligned.m8n8.x4.shared.b16 {%0,%1,%2,%3}, [%4];"
                 : "=r"(r0), "=r"(r1), "=r"(r2), "=r"(r3) : "r"(addr));
}

__device__ __forceinline__ void cp16(void* dst, const void* src) {
    uint32_t d;
    asm("{ .reg .u64 t; cvta.to.shared.u64 t, %1; cvt.u32.u64 %0, t; }" : "=r"(d) : "l"(dst));
    asm volatile("cp.async.cg.shared.global [%0], [%1], 16;" :: "r"(d), "l"(src));
}
#define CP_COMMIT() asm volatile("cp.async.commit_group;" ::: "memory")
#define CP_WAIT(n)  asm volatile("cp.async.wait_group %0;" :: "n"(n) : "memory")

// B swizzled byte address: row n (256B), kb = byte offset in row (0..255, 16B units)
__device__ __forceinline__ uint32_t b_addr(int n, int kb) {
    return (uint32_t)(n * 256 + (kb & 0x8F) + ((((kb >> 4) & 7) ^ (n & 7)) << 4));
}

__device__ __forceinline__ uint32_t smem_u32(const void* p) {
    uint32_t a;
    asm("{ .reg .u64 t; cvta.to.shared.u64 t, %1; cvt.u32.u64 %0, t; }" : "=r"(a) : "l"(p));
    return a;
}

extern __shared__ char dsm[];

__global__ void __launch_bounds__(256, 1) vq_main(
    const float* __restrict__ cb, float* __restrict__ out, int Nq, int write_idx)
{
    __shared__ int s_bi[MT];

    char* As = dsm;                      // fragment-layout A, dedup [z1|z2]
    char* Bs = dsm + A_BYTES;            // three 32KB B slice buffers
    float* redv = reinterpret_cast<float*>(Bs);            // final reduce (reuse B)
    int*   redi = reinterpret_cast<int*>(Bs + MT * 8 * 4);

    const int tid = threadIdx.x;
    const int lane = tid & 31, w = tid >> 5;
    const int wm = w & 3, wn = w >> 2;   // 4 m-groups x 2 n-halves
    const int n0 = blockIdx.x * MT;
    const uint32_t Bs_u32 = smem_u32(Bs);

    // ldmatrix per-lane constants: matrix m = lane>>3, row = lane&7
    // n = wn*64 + ntp*16 + (m>>1)*8 + row  ->  n&7 == lane&7 (all offsets mult of 8)
    const int lm   = lane >> 3;
    const int row8 = lane & 7;
    const uint32_t lane_nbase = (uint32_t)((wn * 64 + ((lm >> 1) << 3) + row8) * 256);
    const uint32_t xor7  = (uint32_t)(row8 << 4);
    const uint32_t klane = (uint32_t)((lm & 1) << 4);

    // ---- build A fragments: A_frag[mt(8)][pkt(32)][lane(32)][4xb32]
    for (int i = tid; i < 8 * 32 * 32; i += 256) {
        int la = i & 31, pkt = (i >> 5) & 31, mt = (i >> 5) >> 5;
        int q  = n0 + mt * 16 + (la >> 2);
        int k0 = pkt * 16 + 2 * (la & 3);
        const char* zr = (const char*)&g_zcat[q][0];
        uint4 v;
        v.x = *(const uint32_t*)(zr + 2 * k0);
        v.y = *(const uint32_t*)(zr + 2 * k0 + 2 * 8 * KPHYS);      // row q+8
        v.z = *(const uint32_t*)(zr + 2 * (k0 + 8));
        v.w = *(const uint32_t*)(zr + 2 * (k0 + 8) + 2 * 8 * KPHYS);
        *reinterpret_cast<uint4*>(As + (size_t)i * 16) = v;
    }

    float acc[2][8][4];
    float bestv[4];
    int   besti[4];
#pragma unroll
    for (int i = 0; i < 4; i++) { bestv[i] = 3.0e38f; besti[i] = 0; }

    // logical slice s -> A physical slice, B k-offset in [e1|e2]
    const int a_ps[SLICES]   = {0, 1, 0, 1, 2, 3};
    const int b_koff[SLICES] = {0, 128, 256, 384, 0, 128};

    // ---- prologue: preload slices g=0 and g=1 into stages 0,1
#pragma unroll
    for (int pg = 0; pg < 2; pg++) {
        char* bd = Bs + pg * B_BYTES;
        const int ks = b_koff[pg];
#pragma unroll
        for (int j = 0; j < 8; j++) {
            int unit = tid + j * 256;
            int n = unit >> 4, u = unit & 15;
            cp16(bd + b_addr(n, u * 16), &g_ecat[n][ks + u * 8]);
        }
        CP_COMMIT();
    }

    int buf = 0, pbuf = 2;
    int s = 0, chunk = 0;
    int sn = 2, cn = 0;                  // slice/chunk of g+2

    for (int g = 0; g < GTOT; g++) {
        CP_WAIT(1);                      // group g complete
        __syncthreads();                 // g visible to all; all done with g-1

        if (g + 2 < GTOT) {              // prefetch g+2 into freed stage
            char* bd = Bs + pbuf * B_BYTES;
            const int c0n = cn * NT, ksn = b_koff[sn];
#pragma unroll
            for (int j = 0; j < 8; j++) {
                int unit = tid + j * 256;
                int n = unit >> 4, u = unit & 15;
                cp16(bd + b_addr(n, u * 16), &g_ecat[c0n + n][ksn + u * 8]);
            }
        }
        CP_COMMIT();

        if (s == 0) {
#pragma unroll
            for (int mt = 0; mt < 2; mt++)
#pragma unroll
                for (int nt = 0; nt < 8; nt++)
#pragma unroll
                    for (int e = 0; e < 4; e++) acc[mt][nt][e] = 0.f;
        }

        const uint32_t bbase = Bs_u32 + (uint32_t)buf * B_BYTES + lane_nbase;
        const int ps8 = a_ps[s] * 8;
#pragma unroll
        for (int ktl = 0; ktl < 8; ktl++) {
            const int pkt = ps8 + ktl;
            uint4 A0 = *reinterpret_cast<const uint4*>(
                As + (((wm * 2 + 0) * 32 + pkt) * 32 + lane) * 16);
            uint4 A1 = *reinterpret_cast<const uint4*>(
                As + (((wm * 2 + 1) * 32 + pkt) * 32 + lane) * 16);
            const uint32_t kb = (uint32_t)(ktl * 32) + klane;
            const uint32_t off = (kb & 0x80u) | ((kb & 0x70u) ^ xor7);
#pragma unroll
            for (int ntp = 0; ntp < 4; ntp++) {
                uint32_t b0, b1, b2, b3;
                ldmatrix_x4(b0, b1, b2, b3,
                            bbase + (uint32_t)(ntp * 4096) + off);
                mma16816(acc[0][2 * ntp],     A0.x, A0.y, A0.z, A0.w, b0, b1);
                mma16816(acc[1][2 * ntp],     A1.x, A1.y, A1.z, A1.w, b0, b1);
                mma16816(acc[0][2 * ntp + 1], A0.x, A0.y, A0.z, A0.w, b2, b3);
                mma16816(acc[1][2 * ntp + 1], A1.x, A1.y, A1.z, A1.w, b2, b3);
            }
        }

        if (s == SLICES - 1) {
            // fold chunk scores into running argmin (ascending index order)
            const int c0 = chunk * NT + wn * 64 + 2 * (lane & 3);
#pragma unroll
            for (int mt = 0; mt < 2; mt++)
#pragma unroll
                for (int nt = 0; nt < 8; nt++) {
                    int cb0 = c0 + nt * 8;
                    float en0 = __ldg(&g_enorm[cb0]);
                    float en1 = __ldg(&g_enorm[cb0 + 1]);
                    float s0 = fmaf(-2.0f, acc[mt][nt][0], en0);
                    float s1 = fmaf(-2.0f, acc[mt][nt][1], en1);
                    float s2 = fmaf(-2.0f, acc[mt][nt][2], en0);
                    float s3 = fmaf(-2.0f, acc[mt][nt][3], en1);
                    int blo = mt * 2, bhi = mt * 2 + 1;
                    if (s0 < bestv[blo]) { bestv[blo] = s0; besti[blo] = cb0; }
                    if (s1 < bestv[blo]) { bestv[blo] = s1; besti[blo] = cb0 + 1; }
                    if (s2 < bestv[bhi]) { bestv[bhi] = s2; besti[bhi] = cb0; }
                    if (s3 < bestv[bhi]) { bestv[bhi] = s3; besti[bhi] = cb0 + 1; }
                }
        }

        buf  = (buf  == STAGES - 1) ? 0 : buf + 1;
        pbuf = (pbuf == STAGES - 1) ? 0 : pbuf + 1;
        if (++s == SLICES) { s = 0; chunk++; }
        if (++sn == SLICES) { sn = 0; cn++; }
    }

    // ---- final cross-thread argmin reduction (lexicographic, first occurrence)
    __syncthreads();
#pragma unroll
    for (int bq = 0; bq < 4; bq++) {
        int q = wm * 32 + (bq >> 1) * 16 + (bq & 1) * 8 + (lane >> 2);
        int slot = wn * 4 + (lane & 3);
        redv[q * 8 + slot] = bestv[bq];
        redi[q * 8 + slot] = besti[bq];
    }
    __syncthreads();
    if (tid < MT) {
        float bv = redv[tid * 8];
        int   bx = redi[tid * 8];
#pragma unroll
        for (int t = 1; t < 8; t++) {
            float v  = redv[tid * 8 + t];
            int   ix = redi[tid * 8 + t];
            if (v < bv || (v == bv && ix < bx)) { bv = v; bx = ix; }
        }
        s_bi[tid] = bx;
        if (write_idx) out[(size_t)Nq * D + n0 + tid] = (float)bx;
    }
    __syncthreads();

    // ---- gather z_q rows from original fp32 codebook
    const float4* cb4 = reinterpret_cast<const float4*>(cb);
    float4* out4 = reinterpret_cast<float4*>(out);
    for (int e = tid; e < MT * (D / 4); e += 256) {
        int q = e >> 6, p = e & 63;
        out4[(size_t)(n0 + q) * (D / 4) + p] = cb4[(size_t)s_bi[q] * (D / 4) + p];
    }
}

extern "C" void kernel_launch(void* const* d_in, const int* in_sizes, int n_in,
                              void* d_out, int out_size) {
    const float* ze = (const float*)d_in[0];
    const float* cb = (const float*)d_in[1];
    float* out = (float*)d_out;

    int Nq = in_sizes[0] / D;                 // 16384
    int nb = Nq / HW;                         // 16
    int write_idx = (out_size >= Nq * D + Nq) ? 1 : 0;

    cudaFuncSetAttribute(vq_main, cudaFuncAttributeMaxDynamicSharedMemorySize, DYN_SMEM);

    eprep_kernel<<<BOOK, 64>>>(cb);
    zprep_kernel<<<dim3(nb, 32), 256>>>(ze);
    vq_main<<<Nq / MT, 256, DYN_SMEM>>>(cb, out, Nq, write_idx);
}